// round 9
// baseline (speedup 1.0000x reference)
#include <cuda_runtime.h>
#include <cuda_fp16.h>
#include <math.h>
#include <stdint.h>

#define NN_MAX 100000
#define NE_MAX 1600000
#define NBA 296                      // persistent grids: 148 SMs x 2 blocks
#define NBB 296

// ---------------- Device scratch ----------------
__device__ __align__(16) __half g_h[(size_t)NN_MAX * 64];   // GEMM out -> gather src
__device__ __align__(16) __half g_a[(size_t)NN_MAX * 64];   // agg out  -> GEMM A src
__device__ float g_dinv[NN_MAX];
__device__ __align__(16) int g_cnt[NN_MAX];
__device__ int   g_rowptr[NN_MAX + 1];
__device__ int   g_cursor[NN_MAX];
__device__ int   g_csr[NE_MAX];
__device__ int   g_bsums[128];
__device__ __align__(16) float g_Wf[64 * 64];
__device__ __align__(16) float g_bf[64];
__device__ int   g_ei_is32;
__device__ unsigned g_barArrive[8];            // zero-init; self-resetting
__device__ unsigned g_barGen[8];               // monotonic across graph replays

// ---------------- grid barrier (gen-counter; replay-safe) ----------------
__device__ __forceinline__ void gbar(int slot, int nb) {
    __syncthreads();
    if (threadIdx.x == 0) {
        __threadfence();
        unsigned g = ((volatile unsigned*)g_barGen)[slot];
        unsigned old = atomicAdd(&g_barArrive[slot], 1);
        if (old == (unsigned)(nb - 1)) {
            g_barArrive[slot] = 0;
            __threadfence();
            atomicAdd(&g_barGen[slot], 1);
        } else {
            while (((volatile unsigned*)g_barGen)[slot] == g) __nanosleep(32);
        }
        __threadfence();
    }
    __syncthreads();
}

__device__ __forceinline__ int edge_val(const int* __restrict__ w, size_t e, bool is32) {
    return is32 ? w[e] : w[2 * e];
}

// ---------------- csrA: zero + detect + wfuse/bfuse | gbar | hist ----------------
__global__ __launch_bounds__(256) void csrA(
    const int* __restrict__ ei, int nwords, int n, int ne,
    const float* __restrict__ W3, const float* __restrict__ W4,
    const float* __restrict__ b3, const float* __restrict__ b4) {
    int t = threadIdx.x, b = blockIdx.x;
    int gtid = b * 256 + t;
    const int GSZ = NBA * 256;

    for (int i = gtid; i < n; i += GSZ) g_cnt[i] = 0;
    if (b == NBA - 1) {
        __shared__ int any;
        if (t == 0) any = 0;
        __syncthreads();
        int idx = 2 * t + 1;                       // odd words: 0 iff int64 (<2^31)
        if (idx < nwords && ei[idx] != 0) atomicOr(&any, 1);
        __syncthreads();
        if (t == 0) g_ei_is32 = any;
    }
    for (int e2 = gtid; e2 < 64 * 64; e2 += GSZ) {
        int i = e2 >> 6, j = e2 & 63;
        float acc = 0.f;
        for (int k = 0; k < 256; k++) acc += W3[i * 256 + k] * W4[k * 64 + j];
        g_Wf[e2] = acc;
    }
    if (gtid < 64) {
        float acc = b4[gtid];
        for (int k = 0; k < 256; k++) acc += b3[k] * W4[k * 64 + gtid];
        g_bf[gtid] = acc;
    }
    gbar(0, NBA);

    bool is32 = (g_ei_is32 != 0);
    for (int e = gtid; e < ne; e += GSZ) {
        int dst = edge_val(ei, (size_t)ne + e, is32);
        atomicAdd(&g_cnt[dst], 1);
    }
}

// ---------------- csrB: tile scan | gbar | top scan | gbar | apply | gbar | fill -----------
__global__ __launch_bounds__(256) void csrB(const int* __restrict__ ei, int n, int ne) {
    int t = threadIdx.x, b = blockIdx.x;
    int lane = t & 31, wid = t >> 5;
    const int NTILES = (n + 1023) >> 10;          // 98 tiles of 1024 (256 thr x 4)
    __shared__ int wsum[8];

    int v[4] = {0, 0, 0, 0};
    int exc_t = 0;
    bool active = (b < NTILES);
    int base = b * 1024 + t * 4;

    if (active) {
        if (base + 3 < n) {
            int4 r = *(const int4*)(g_cnt + base);
            v[0] = r.x; v[1] = r.y; v[2] = r.z; v[3] = r.w;
        } else {
#pragma unroll
            for (int q = 0; q < 4; q++) v[q] = (base + q < n) ? g_cnt[base + q] : 0;
        }
        int tsum = v[0] + v[1] + v[2] + v[3];
        int x = tsum;
#pragma unroll
        for (int off = 1; off < 32; off <<= 1) {
            int y = __shfl_up_sync(0xffffffffu, x, off);
            if (lane >= off) x += y;
        }
        if (lane == 31) wsum[wid] = x;
        __syncthreads();
        if (wid == 0) {
            int s = (lane < 8) ? wsum[lane] : 0;
#pragma unroll
            for (int off = 1; off < 8; off <<= 1) {
                int y = __shfl_up_sync(0xffffffffu, s, off);
                if (lane >= off) s += y;
            }
            if (lane < 8) wsum[lane] = s;
        }
        __syncthreads();
        int wpre = wid ? wsum[wid - 1] : 0;
        exc_t = wpre + x - tsum;                  // thread-exclusive within tile
        if (t == 0) g_bsums[b] = wsum[7];         // tile total
    }
    gbar(1, NBB);

    if (b == 0) {                                  // exclusive scan of tile totals
        __shared__ int sm2[128];
        int val = (t < NTILES) ? g_bsums[t] : 0;
        if (t < 128) sm2[t] = val;
        __syncthreads();
        for (int off = 1; off < 128; off <<= 1) {
            int add = (t >= off && t < 128) ? sm2[t - off] : 0;
            __syncthreads();
            if (t < 128) sm2[t] += add;
            __syncthreads();
        }
        if (t < NTILES) g_bsums[t] = sm2[t] - val;
    }
    gbar(2, NBB);

    if (active) {
        int run = g_bsums[b] + exc_t;
#pragma unroll
        for (int q = 0; q < 4; q++) {
            int i = base + q;
            if (i < n) {
                g_rowptr[i] = run;
                g_cursor[i] = run;
                g_dinv[i] = rsqrtf((float)v[q] + 1.0f);
            }
            run += v[q];
        }
    }
    if (b == 0 && t == 0) g_rowptr[n] = ne;
    gbar(3, NBB);

    bool is32 = (g_ei_is32 != 0);
    const int GSZ = NBB * 256;
    for (int e = b * 256 + t; e < ne; e += GSZ) {
        int src = edge_val(ei, (size_t)e, is32);
        int dst = edge_val(ei, (size_t)ne + e, is32);
        int p = atomicAdd(&g_cursor[dst], 1);
        g_csr[p] = src;
    }
}

// ---------------- fp16 tensor-core GEMM: mma.m16n8k16 + ldmatrix ----------------
#define MMA_F16(d, A0, A1, A2, A3, B0, B1)                                      \
    asm("mma.sync.aligned.m16n8k16.row.col.f32.f16.f16.f32 "                    \
        "{%0,%1,%2,%3}, {%4,%5,%6,%7}, {%8,%9}, {%0,%1,%2,%3};"                 \
        : "+f"(d[0]), "+f"(d[1]), "+f"(d[2]), "+f"(d[3])                        \
        : "r"(A0), "r"(A1), "r"(A2), "r"(A3), "r"(B0), "r"(B1))

template <int K, int EPI, typename InT, typename OutT>
__global__ __launch_bounds__(256, 3) void gemm_mma(
    const InT* __restrict__ A, const float* __restrict__ W,
    const float* __restrict__ extra, OutT* __restrict__ C, int M) {
    constexpr int ASTRIDE = K + 8;                // halfs
    extern __shared__ uint32_t smem[];
    uint32_t* sB = smem;                          // (K/16)*8 frags x 32 lanes x 2 regs
    __half*   As = (__half*)(smem + K * 32);      // 128 x ASTRIDE halfs

    int tid = threadIdx.x, lane = tid & 31, warp = tid >> 5;
    int rowBase = blockIdx.x * 128;
    int gr = lane >> 2;
    int gc = lane & 3;

    for (int i = tid; i < K * 32; i += 256) {
        int f = i >> 6, within = i & 63;
        int bl = within >> 1, r = within & 1;
        int k = (f >> 3) * 16 + (bl & 3) * 2 + r * 8;
        int n = (f & 7) * 8 + (bl >> 2);
        half2 h = __floats2half2_rn(W[k * 64 + n], W[(k + 1) * 64 + n]);
        sB[i] = *(uint32_t*)&h;
    }

    {
        int row = tid >> 1;
        int off = (tid & 1) * (K / 2);
        int grow = rowBase + row;
        half2* dst = (half2*)(As + row * ASTRIDE + off);
        if (grow < M) {
            if constexpr (sizeof(InT) == 4) {
                const float4* src = (const float4*)((const float*)A + (size_t)grow * K + off);
#pragma unroll
                for (int q = 0; q < K / 8; q++) {
                    float4 v = src[q];
                    dst[2 * q]     = __floats2half2_rn(v.x, v.y);
                    dst[2 * q + 1] = __floats2half2_rn(v.z, v.w);
                }
            } else {
                const uint4* src = (const uint4*)((const __half*)A + (size_t)grow * K + off);
#pragma unroll
                for (int q = 0; q < K / 16; q++) {
                    ((uint4*)dst)[q] = src[q];
                }
            }
        } else {
#pragma unroll
            for (int q = 0; q < K / 4; q++) dst[q] = __floats2half2_rn(0.f, 0.f);
        }
    }

    float acc[8][4];
#pragma unroll
    for (int nt = 0; nt < 8; nt++)
#pragma unroll
        for (int r = 0; r < 4; r++) acc[nt][r] = 0.f;

    int rowLoc = warp * 16;
    __syncthreads();

    int lrow = rowLoc + (lane & 15);
    int lcol = (lane >> 4) << 3;

#pragma unroll
    for (int kc16 = 0; kc16 < K / 16; kc16++) {
        uint32_t a0, a1, a2, a3;
        uint32_t addr = (uint32_t)__cvta_generic_to_shared(
            &As[lrow * ASTRIDE + kc16 * 16 + lcol]);
        asm volatile("ldmatrix.sync.aligned.m8n8.x4.shared.b16 {%0,%1,%2,%3}, [%4];"
                     : "=r"(a0), "=r"(a1), "=r"(a2), "=r"(a3) : "r"(addr));
#pragma unroll
        for (int nt = 0; nt < 8; nt++) {
            int sbase = ((kc16 * 8 + nt) * 32 + lane) * 2;
            MMA_F16(acc[nt], a0, a1, a2, a3, sB[sbase], sB[sbase + 1]);
        }
    }

    int row0 = rowBase + rowLoc + gr;
    int row1 = row0 + 8;

    if (EPI == 0) {
        __half* Ch = (__half*)C;
        if (row0 < M) {
#pragma unroll
            for (int nt = 0; nt < 8; nt++)
                *(half2*)(Ch + (size_t)row0 * 64 + nt * 8 + 2 * gc) =
                    __floats2half2_rn(acc[nt][0], acc[nt][1]);
        }
        if (row1 < M) {
#pragma unroll
            for (int nt = 0; nt < 8; nt++)
                *(half2*)(Ch + (size_t)row1 * 64 + nt * 8 + 2 * gc) =
                    __floats2half2_rn(acc[nt][2], acc[nt][3]);
        }
    } else {
        float* Cf = (float*)C;
        float v0[16], v1[16];
#pragma unroll
        for (int nt = 0; nt < 8; nt++) {
            float2 bb = *(const float2*)(extra + nt * 8 + 2 * gc);
            v0[2*nt]   = acc[nt][0] + bb.x;
            v0[2*nt+1] = acc[nt][1] + bb.y;
            v1[2*nt]   = acc[nt][2] + bb.x;
            v1[2*nt+1] = acc[nt][3] + bb.y;
        }
        float m0 = -1e30f, m1 = -1e30f;
#pragma unroll
        for (int i = 0; i < 16; i++) { m0 = fmaxf(m0, v0[i]); m1 = fmaxf(m1, v1[i]); }
        m0 = fmaxf(m0, __shfl_xor_sync(0xffffffffu, m0, 1));
        m0 = fmaxf(m0, __shfl_xor_sync(0xffffffffu, m0, 2));
        m1 = fmaxf(m1, __shfl_xor_sync(0xffffffffu, m1, 1));
        m1 = fmaxf(m1, __shfl_xor_sync(0xffffffffu, m1, 2));
        float s0 = 0.f, s1 = 0.f;
#pragma unroll
        for (int i = 0; i < 16; i++) { s0 += expf(v0[i] - m0); s1 += expf(v1[i] - m1); }
        s0 += __shfl_xor_sync(0xffffffffu, s0, 1);
        s0 += __shfl_xor_sync(0xffffffffu, s0, 2);
        s1 += __shfl_xor_sync(0xffffffffu, s1, 1);
        s1 += __shfl_xor_sync(0xffffffffu, s1, 2);
        float lse0 = m0 + logf(s0);
        float lse1 = m1 + logf(s1);
        if (row0 < M) {
#pragma unroll
            for (int nt = 0; nt < 8; nt++)
                *(float2*)(Cf + (size_t)row0 * 64 + nt * 8 + 2 * gc) =
                    make_float2(v0[2*nt] - lse0, v0[2*nt+1] - lse0);
        }
        if (row1 < M) {
#pragma unroll
            for (int nt = 0; nt < 8; nt++)
                *(float2*)(Cf + (size_t)row1 * 64 + nt * 8 + 2 * gc) =
                    make_float2(v1[2*nt] - lse1, v1[2*nt+1] - lse1);
        }
    }
}

// ---------------- Aggregation (fp16 in, fp16 out) ----------------
__global__ void agg_k(const __half* __restrict__ hs, const float* __restrict__ bias,
                      __half* __restrict__ out, int M) {
    __shared__ int   sidx[8][32];
    __shared__ float sds[8][32];
    int wib = threadIdx.x >> 5;
    int w = (blockIdx.x * blockDim.x + threadIdx.x) >> 5;
    int lane = threadIdx.x & 31;
    if (w >= M) return;

    int start = g_rowptr[w];
    int end = g_rowptr[w + 1];
    float rd = g_dinv[w];

    float2 selfv = __half22float2(((const half2*)(hs + (size_t)w * 64))[lane]);
    float a0 = rd * selfv.x, a1 = rd * selfv.y;
    float b0 = 0.f, b1 = 0.f, c0 = 0.f, c1 = 0.f, d0 = 0.f, d1 = 0.f;
    float e0 = 0.f, e1 = 0.f, f0 = 0.f, f1 = 0.f;
    float g0 = 0.f, g1 = 0.f, h0 = 0.f, h1 = 0.f;

    for (int base = start; base < end; base += 32) {
        int e = base + lane;
        __syncwarp();
        int s = (e < end) ? g_csr[e] : 0;
        sidx[wib][lane] = s;
        sds[wib][lane] = (e < end) ? g_dinv[s] : 0.f;
        __syncwarp();
        int cnt = min(32, end - base);
        int j = 0;
        for (; j + 8 <= cnt; j += 8) {
            half2 v0 = ((const half2*)(hs + (size_t)sidx[wib][j + 0] * 64))[lane];
            half2 v1 = ((const half2*)(hs + (size_t)sidx[wib][j + 1] * 64))[lane];
            half2 v2 = ((const half2*)(hs + (size_t)sidx[wib][j + 2] * 64))[lane];
            half2 v3 = ((const half2*)(hs + (size_t)sidx[wib][j + 3] * 64))[lane];
            half2 v4 = ((const half2*)(hs + (size_t)sidx[wib][j + 4] * 64))[lane];
            half2 v5 = ((const half2*)(hs + (size_t)sidx[wib][j + 5] * 64))[lane];
            half2 v6 = ((const half2*)(hs + (size_t)sidx[wib][j + 6] * 64))[lane];
            half2 v7 = ((const half2*)(hs + (size_t)sidx[wib][j + 7] * 64))[lane];
            float2 f0v = __half22float2(v0), f1v = __half22float2(v1);
            float2 f2v = __half22float2(v2), f3v = __half22float2(v3);
            float2 f4v = __half22float2(v4), f5v = __half22float2(v5);
            float2 f6v = __half22float2(v6), f7v = __half22float2(v7);
            a0 = fmaf(f0v.x, sds[wib][j+0], a0); a1 = fmaf(f0v.y, sds[wib][j+0], a1);
            b0 = fmaf(f1v.x, sds[wib][j+1], b0); b1 = fmaf(f1v.y, sds[wib][j+1], b1);
            c0 = fmaf(f2v.x, sds[wib][j+2], c0); c1 = fmaf(f2v.y, sds[wib][j+2], c1);
            d0 = fmaf(f3v.x, sds[wib][j+3], d0); d1 = fmaf(f3v.y, sds[wib][j+3], d1);
            e0 = fmaf(f4v.x, sds[wib][j+4], e0); e1 = fmaf(f4v.y, sds[wib][j+4], e1);
            f0 = fmaf(f5v.x, sds[wib][j+5], f0); f1 = fmaf(f5v.y, sds[wib][j+5], f1);
            g0 = fmaf(f6v.x, sds[wib][j+6], g0); g1 = fmaf(f6v.y, sds[wib][j+6], g1);
            h0 = fmaf(f7v.x, sds[wib][j+7], h0); h1 = fmaf(f7v.y, sds[wib][j+7], h1);
        }
        for (; j < cnt; j++) {
            float2 fv = __half22float2(((const half2*)(hs + (size_t)sidx[wib][j] * 64))[lane]);
            float ss = sds[wib][j];
            a0 = fmaf(fv.x, ss, a0);
            a1 = fmaf(fv.y, ss, a1);
        }
    }
    a0 = ((a0 + b0) + (c0 + d0)) + ((e0 + f0) + (g0 + h0));
    a1 = ((a1 + b1) + (c1 + d1)) + ((e1 + f1) + (g1 + h1));

    float2 bb = ((const float2*)bias)[lane];
    float o0 = fmaxf(fmaf(a0, rd, bb.x), 0.f);
    float o1 = fmaxf(fmaf(a1, rd, bb.y), 0.f);
    ((half2*)(out + (size_t)w * 64))[lane] = __floats2half2_rn(o0, o1);
}

// ---------------- Side-stream context ----------------
struct SideCtx {
    cudaStream_t side;
    cudaEvent_t evFork, evG1;
    SideCtx() {
        cudaStreamCreateWithFlags(&side, cudaStreamNonBlocking);
        cudaEventCreateWithFlags(&evFork, cudaEventDisableTiming);
        cudaEventCreateWithFlags(&evG1, cudaEventDisableTiming);
    }
};
static SideCtx g_ctx;

// ---------------- Host launcher ----------------
extern "C" void kernel_launch(void* const* d_in, const int* in_sizes, int n_in,
                              void* d_out, int out_size) {
    const float* x  = (const float*)d_in[0];
    const int*   ei = (const int*)d_in[1];
    const float* W1 = (const float*)d_in[2];
    const float* b1 = (const float*)d_in[3];
    const float* W2 = (const float*)d_in[4];
    const float* b2 = (const float*)d_in[5];
    const float* W3 = (const float*)d_in[6];
    const float* b3 = (const float*)d_in[7];
    const float* W4 = (const float*)d_in[8];
    const float* b4 = (const float*)d_in[9];
    float* out = (float*)d_out;

    const int M = in_sizes[0] / 128;
    const int E = in_sizes[1] / 2;

    __half *hb, *ab;
    float *Wf, *bf;
    cudaGetSymbolAddress((void**)&hb, g_h);
    cudaGetSymbolAddress((void**)&ab, g_a);
    cudaGetSymbolAddress((void**)&Wf, g_Wf);
    cudaGetSymbolAddress((void**)&bf, g_bf);

    const int smem128 = 128 * 32 * 4 + 128 * 136 * 2;   // 51200 B
    const int smem64  = 64 * 32 * 4 + 128 * 72 * 2;     // 26624 B
    cudaFuncSetAttribute((const void*)gemm_mma<128, 0, float, __half>,
                         cudaFuncAttributeMaxDynamicSharedMemorySize, smem128);
    cudaFuncSetAttribute((const void*)gemm_mma<64, 0, __half, __half>,
                         cudaFuncAttributeMaxDynamicSharedMemorySize, smem64);
    cudaFuncSetAttribute((const void*)gemm_mma<64, 1, __half, float>,
                         cudaFuncAttributeMaxDynamicSharedMemorySize, smem64);

    const int gemmBlocks = (M + 127) / 128;
    const int warpBlocks = (M * 32 + 255) / 256;

    // Fork: GEMM1 (no CSR dependency) on side stream || CSR build on main stream.
    cudaEventRecord(g_ctx.evFork, 0);
    cudaStreamWaitEvent(g_ctx.side, g_ctx.evFork, 0);
    gemm_mma<128, 0, float, __half><<<gemmBlocks, 256, smem128, g_ctx.side>>>(x, W1, nullptr, hb, M);
    cudaEventRecord(g_ctx.evG1, g_ctx.side);

    csrA<<<NBA, 256>>>(ei, 2 * E, M, E, W3, W4, b3, b4);
    csrB<<<NBB, 256>>>(ei, M, E);

    cudaStreamWaitEvent(0, g_ctx.evG1, 0);
    agg_k<<<warpBlocks, 256>>>(hb, b1, ab, M);     // launch #4 -> ncu capture slot
    gemm_mma<64, 0, __half, __half><<<gemmBlocks, 256, smem64>>>(ab, W2, nullptr, hb, M);
    agg_k<<<warpBlocks, 256>>>(hb, b2, ab, M);
    gemm_mma<64, 1, __half, float><<<gemmBlocks, 256, smem64>>>(ab, Wf, bf, out, M);
}

// round 10
// speedup vs baseline: 1.2282x; 1.2282x over previous
#include <cuda_runtime.h>
#include <cuda_fp16.h>
#include <math.h>
#include <stdint.h>

#define NN_MAX 100000
#define NE_MAX 1600000

// ---------------- Device scratch ----------------
__device__ __align__(16) __half g_h[(size_t)NN_MAX * 64];   // GEMM out (dinv-scaled) -> gather src
__device__ __align__(16) __half g_a[(size_t)NN_MAX * 64];   // agg out  -> GEMM A src
__device__ float g_dinv[NN_MAX];
__device__ __align__(16) int g_cnt[NN_MAX];
__device__ int   g_rowptr[NN_MAX + 1];
__device__ int   g_cursor[NN_MAX];
__device__ int   g_csr[NE_MAX];                 // BYTE offsets (src*128)
__device__ __align__(16) float g_Wf[64 * 64];
__device__ __align__(16) float g_bf[64];
__device__ int   g_ei_is32;
__device__ int   g_ticket;
__device__ unsigned long long g_state[128];

// ---------------- prep: zero cnt + detect dtype + reset scan state + W3@W4 fusion ----------
__global__ void prep_k(const int* __restrict__ ei, int nwords, int M,
                       const float* __restrict__ W3, const float* __restrict__ W4,
                       const float* __restrict__ b3, const float* __restrict__ b4) {
    int b = blockIdx.x, t = threadIdx.x;
    int NBZ = (M + 255) >> 8;
    if (b < NBZ) {
        int i = b * 256 + t;
        if (i < M) g_cnt[i] = 0;
        return;
    }
    if (b == NBZ) {
        __shared__ int any;
        if (t == 0) { any = 0; g_ticket = 0; }
        __syncthreads();
        int idx = 2 * t + 1;                       // odd words: 0 iff int64 (<2^31)
        if (idx < nwords && ei[idx] != 0) atomicOr(&any, 1);
        if (t < 128) g_state[t] = 0ULL;
        if (t < 64) {
            float acc = b4[t];
            for (int k = 0; k < 256; k++) acc += b3[k] * W4[k * 64 + t];
            g_bf[t] = acc;
        }
        __syncthreads();
        if (t == 0) g_ei_is32 = any;
        return;
    }
    int e = (b - NBZ - 1) * 256 + t;
    int i = e >> 6, j = e & 63;
    float acc = 0.f;
    for (int k = 0; k < 256; k++) acc += W3[i * 256 + k] * W4[k * 64 + j];
    g_Wf[e] = acc;
}

__device__ __forceinline__ int edge_val(const int* __restrict__ w, size_t e, bool is32) {
    return is32 ? w[e] : w[2 * e];
}

__global__ void hist_k(const int* __restrict__ w, int ne) {
    int e = blockIdx.x * blockDim.x + threadIdx.x;
    if (e < ne) {
        bool is32 = (g_ei_is32 != 0);
        int dst = edge_val(w, (size_t)ne + e, is32);
        atomicAdd(&g_cnt[dst], 1);
    }
}

// ---------------- single-pass decoupled-lookback scan ----------------
__global__ void scan_k(int n, int ne) {
    __shared__ int wsum[32];
    __shared__ int sbid;
    __shared__ int sexc;
    int t = threadIdx.x, lane = t & 31, wid = t >> 5;
    if (t == 0) sbid = atomicAdd(&g_ticket, 1);
    __syncthreads();
    int bid = sbid;
    int i = bid * 1024 + t;
    int v = (i < n) ? g_cnt[i] : 0;
    int x = v;
#pragma unroll
    for (int off = 1; off < 32; off <<= 1) {
        int y = __shfl_up_sync(0xffffffffu, x, off);
        if (lane >= off) x += y;
    }
    if (lane == 31) wsum[wid] = x;
    __syncthreads();
    if (wid == 0) {
        int s = wsum[lane];
#pragma unroll
        for (int off = 1; off < 32; off <<= 1) {
            int y = __shfl_up_sync(0xffffffffu, s, off);
            if (lane >= off) s += y;
        }
        wsum[lane] = s;
    }
    __syncthreads();
    int wpre = wid ? wsum[wid - 1] : 0;
    int incl = wpre + x;
    int total = wsum[31];

    if (t == 0) {
        unsigned long long pub = (bid == 0)
            ? ((2ULL << 32) | (unsigned)total)
            : ((1ULL << 32) | (unsigned)total);
        atomicExch(&g_state[bid], pub);
    }
    if (wid == 0) {
        int exc = 0;
        if (bid > 0) {
            int p = bid - 1;
            while (true) {
                int idx = p - lane;
                bool valid = idx >= 0;
                unsigned long long s;
                do {
                    s = valid ? atomicAdd(&g_state[idx], 0ULL) : (2ULL << 32);
                } while (__any_sync(0xffffffffu, (unsigned)(s >> 32) == 0u));
                unsigned pm = __ballot_sync(0xffffffffu, valid && (unsigned)(s >> 32) == 2u);
                int contrib;
                if (pm) {
                    int fp = __ffs(pm) - 1;
                    contrib = (valid && lane <= fp) ? (int)(unsigned)s : 0;
                } else {
                    contrib = valid ? (int)(unsigned)s : 0;
                }
#pragma unroll
                for (int o = 16; o > 0; o >>= 1) contrib += __shfl_xor_sync(0xffffffffu, contrib, o);
                exc += contrib;
                if (pm) break;
                p -= 32;
                if (p < 0) break;
            }
        }
        if (lane == 0) {
            sexc = exc;
            atomicExch(&g_state[bid], (2ULL << 32) | (unsigned)(exc + total));
        }
    }
    __syncthreads();
    int rp = sexc + incl - v;
    if (i < n) {
        g_rowptr[i] = rp;
        g_cursor[i] = rp;
        g_dinv[i] = rsqrtf((float)v + 1.0f);
    }
    if (t == 0 && bid == 0) g_rowptr[n] = ne;
}

__global__ void fill_k(const int* __restrict__ w, int ne) {
    int e = blockIdx.x * blockDim.x + threadIdx.x;
    if (e < ne) {
        bool is32 = (g_ei_is32 != 0);
        int src = edge_val(w, (size_t)e, is32);
        int dst = edge_val(w, (size_t)ne + e, is32);
        int p = atomicAdd(&g_cursor[dst], 1);
        g_csr[p] = src << 7;                       // byte offset (64 halfs * 2B)
    }
}

// ---------------- scale hs by dinv (post-join, for GEMM1's output) ----------------
// Thread handles 16 bytes = 8 halfs; 8 threads per row.
__global__ void scale_k(__half* __restrict__ hs, int M) {
    int i = blockIdx.x * blockDim.x + threadIdx.x;
    if (i >= M * 8) return;
    int row = i >> 3;
    float rd = g_dinv[row];
    uint4 v = ((uint4*)hs)[i];
    half2* h = (half2*)&v;
#pragma unroll
    for (int q = 0; q < 4; q++) {
        float2 f = __half22float2(h[q]);
        h[q] = __floats2half2_rn(f.x * rd, f.y * rd);
    }
    ((uint4*)hs)[i] = v;
}

// ---------------- fp16 tensor-core GEMM: mma.m16n8k16 + ldmatrix ----------------
// EPI 0: C (half) = [dinv[row] *] (A@W)   (scaled iff extra != nullptr)
// EPI 1: C (float) = log_softmax(A@W + bias)
#define MMA_F16(d, A0, A1, A2, A3, B0, B1)                                      \
    asm("mma.sync.aligned.m16n8k16.row.col.f32.f16.f16.f32 "                    \
        "{%0,%1,%2,%3}, {%4,%5,%6,%7}, {%8,%9}, {%0,%1,%2,%3};"                 \
        : "+f"(d[0]), "+f"(d[1]), "+f"(d[2]), "+f"(d[3])                        \
        : "r"(A0), "r"(A1), "r"(A2), "r"(A3), "r"(B0), "r"(B1))

template <int K, int EPI, typename InT, typename OutT>
__global__ __launch_bounds__(256, 3) void gemm_mma(
    const InT* __restrict__ A, const float* __restrict__ W,
    const float* __restrict__ extra, OutT* __restrict__ C, int M) {
    constexpr int ASTRIDE = K + 8;                // halfs
    extern __shared__ uint32_t smem[];
    uint32_t* sB = smem;
    __half*   As = (__half*)(smem + K * 32);

    int tid = threadIdx.x, lane = tid & 31, warp = tid >> 5;
    int rowBase = blockIdx.x * 128;
    int gr = lane >> 2;
    int gc = lane & 3;

    for (int i = tid; i < K * 32; i += 256) {
        int f = i >> 6, within = i & 63;
        int bl = within >> 1, r = within & 1;
        int k = (f >> 3) * 16 + (bl & 3) * 2 + r * 8;
        int n = (f & 7) * 8 + (bl >> 2);
        half2 h = __floats2half2_rn(W[k * 64 + n], W[(k + 1) * 64 + n]);
        sB[i] = *(uint32_t*)&h;
    }

    {
        int row = tid >> 1;
        int off = (tid & 1) * (K / 2);
        int grow = rowBase + row;
        half2* dst = (half2*)(As + row * ASTRIDE + off);
        if (grow < M) {
            if constexpr (sizeof(InT) == 4) {
                const float4* src = (const float4*)((const float*)A + (size_t)grow * K + off);
#pragma unroll
                for (int q = 0; q < K / 8; q++) {
                    float4 v = src[q];
                    dst[2 * q]     = __floats2half2_rn(v.x, v.y);
                    dst[2 * q + 1] = __floats2half2_rn(v.z, v.w);
                }
            } else {
                const uint4* src = (const uint4*)((const __half*)A + (size_t)grow * K + off);
#pragma unroll
                for (int q = 0; q < K / 16; q++) ((uint4*)dst)[q] = src[q];
            }
        } else {
#pragma unroll
            for (int q = 0; q < K / 4; q++) dst[q] = __floats2half2_rn(0.f, 0.f);
        }
    }

    float acc[8][4];
#pragma unroll
    for (int nt = 0; nt < 8; nt++)
#pragma unroll
        for (int r = 0; r < 4; r++) acc[nt][r] = 0.f;

    int rowLoc = warp * 16;
    __syncthreads();

    int lrow = rowLoc + (lane & 15);
    int lcol = (lane >> 4) << 3;

#pragma unroll
    for (int kc16 = 0; kc16 < K / 16; kc16++) {
        uint32_t a0, a1, a2, a3;
        uint32_t addr = (uint32_t)__cvta_generic_to_shared(
            &As[lrow * ASTRIDE + kc16 * 16 + lcol]);
        asm volatile("ldmatrix.sync.aligned.m8n8.x4.shared.b16 {%0,%1,%2,%3}, [%4];"
                     : "=r"(a0), "=r"(a1), "=r"(a2), "=r"(a3) : "r"(addr));
#pragma unroll
        for (int nt = 0; nt < 8; nt++) {
            int sbase = ((kc16 * 8 + nt) * 32 + lane) * 2;
            MMA_F16(acc[nt], a0, a1, a2, a3, sB[sbase], sB[sbase + 1]);
        }
    }

    int row0 = rowBase + rowLoc + gr;
    int row1 = row0 + 8;

    if (EPI == 0) {
        __half* Ch = (__half*)C;
        if (row0 < M) {
            float s = extra ? extra[row0] : 1.f;
#pragma unroll
            for (int nt = 0; nt < 8; nt++)
                *(half2*)(Ch + (size_t)row0 * 64 + nt * 8 + 2 * gc) =
                    __floats2half2_rn(acc[nt][0] * s, acc[nt][1] * s);
        }
        if (row1 < M) {
            float s = extra ? extra[row1] : 1.f;
#pragma unroll
            for (int nt = 0; nt < 8; nt++)
                *(half2*)(Ch + (size_t)row1 * 64 + nt * 8 + 2 * gc) =
                    __floats2half2_rn(acc[nt][2] * s, acc[nt][3] * s);
        }
    } else {
        float* Cf = (float*)C;
        float v0[16], v1[16];
#pragma unroll
        for (int nt = 0; nt < 8; nt++) {
            float2 bb = *(const float2*)(extra + nt * 8 + 2 * gc);
            v0[2*nt]   = acc[nt][0] + bb.x;
            v0[2*nt+1] = acc[nt][1] + bb.y;
            v1[2*nt]   = acc[nt][2] + bb.x;
            v1[2*nt+1] = acc[nt][3] + bb.y;
        }
        float m0 = -1e30f, m1 = -1e30f;
#pragma unroll
        for (int i = 0; i < 16; i++) { m0 = fmaxf(m0, v0[i]); m1 = fmaxf(m1, v1[i]); }
        m0 = fmaxf(m0, __shfl_xor_sync(0xffffffffu, m0, 1));
        m0 = fmaxf(m0, __shfl_xor_sync(0xffffffffu, m0, 2));
        m1 = fmaxf(m1, __shfl_xor_sync(0xffffffffu, m1, 1));
        m1 = fmaxf(m1, __shfl_xor_sync(0xffffffffu, m1, 2));
        float s0 = 0.f, s1 = 0.f;
#pragma unroll
        for (int i = 0; i < 16; i++) { s0 += expf(v0[i] - m0); s1 += expf(v1[i] - m1); }
        s0 += __shfl_xor_sync(0xffffffffu, s0, 1);
        s0 += __shfl_xor_sync(0xffffffffu, s0, 2);
        s1 += __shfl_xor_sync(0xffffffffu, s1, 1);
        s1 += __shfl_xor_sync(0xffffffffu, s1, 2);
        float lse0 = m0 + logf(s0);
        float lse1 = m1 + logf(s1);
        if (row0 < M) {
#pragma unroll
            for (int nt = 0; nt < 8; nt++)
                *(float2*)(Cf + (size_t)row0 * 64 + nt * 8 + 2 * gc) =
                    make_float2(v0[2*nt] - lse0, v0[2*nt+1] - lse0);
        }
        if (row1 < M) {
#pragma unroll
            for (int nt = 0; nt < 8; nt++)
                *(float2*)(Cf + (size_t)row1 * 64 + nt * 8 + 2 * gc) =
                    make_float2(v1[2*nt] - lse1, v1[2*nt+1] - lse1);
        }
    }
}

// ---------------- Aggregation v2: hs pre-scaled; byte-offset CSR; HADD2 accumulators ------
// out = relu( rd * (Σ_edges hs_src + hs_self) + bias )
__global__ void agg_k(const __half* __restrict__ hs, const float* __restrict__ bias,
                      __half* __restrict__ out, int M) {
    __shared__ int soff[8][32];
    int wib = threadIdx.x >> 5;
    int w = (blockIdx.x * blockDim.x + threadIdx.x) >> 5;
    int lane = threadIdx.x & 31;
    if (w >= M) return;

    int start = g_rowptr[w];
    int end = g_rowptr[w + 1];
    float rd = g_dinv[w];

    const char* basep = (const char*)hs + lane * 4;   // this lane's half2 column
    float2 selfv = __half22float2(*(const half2*)(basep + ((size_t)w << 7)));
    float a0 = selfv.x, a1 = selfv.y;

    half2 z = __floats2half2_rn(0.f, 0.f);
    half2 q0 = z, q1 = z, q2 = z, q3 = z, q4 = z, q5 = z, q6 = z, q7 = z;

    for (int base = start; base < end; base += 32) {
        int e = base + lane;
        __syncwarp();
        soff[wib][lane] = (e < end) ? g_csr[e] : 0;
        __syncwarp();
        int cnt = min(32, end - base);
        int j = 0;
        for (; j + 8 <= cnt; j += 8) {
            half2 v0 = *(const half2*)(basep + soff[wib][j + 0]);
            half2 v1 = *(const half2*)(basep + soff[wib][j + 1]);
            half2 v2 = *(const half2*)(basep + soff[wib][j + 2]);
            half2 v3 = *(const half2*)(basep + soff[wib][j + 3]);
            half2 v4 = *(const half2*)(basep + soff[wib][j + 4]);
            half2 v5 = *(const half2*)(basep + soff[wib][j + 5]);
            half2 v6 = *(const half2*)(basep + soff[wib][j + 6]);
            half2 v7 = *(const half2*)(basep + soff[wib][j + 7]);
            q0 = __hadd2(q0, v0); q1 = __hadd2(q1, v1);
            q2 = __hadd2(q2, v2); q3 = __hadd2(q3, v3);
            q4 = __hadd2(q4, v4); q5 = __hadd2(q5, v5);
            q6 = __hadd2(q6, v6); q7 = __hadd2(q7, v7);
        }
        for (; j < cnt; j++) {
            float2 fv = __half22float2(*(const half2*)(basep + soff[wib][j]));
            a0 += fv.x;
            a1 += fv.y;
        }
    }
    // Reduce fp16 partials in fp32.
    float2 r0 = __half22float2(q0), r1 = __half22float2(q1);
    float2 r2 = __half22float2(q2), r3 = __half22float2(q3);
    float2 r4 = __half22float2(q4), r5 = __half22float2(q5);
    float2 r6 = __half22float2(q6), r7 = __half22float2(q7);
    a0 += ((r0.x + r1.x) + (r2.x + r3.x)) + ((r4.x + r5.x) + (r6.x + r7.x));
    a1 += ((r0.y + r1.y) + (r2.y + r3.y)) + ((r4.y + r5.y) + (r6.y + r7.y));

    float2 bb = ((const float2*)bias)[lane];
    float o0 = fmaxf(fmaf(a0, rd, bb.x), 0.f);
    float o1 = fmaxf(fmaf(a1, rd, bb.y), 0.f);
    ((half2*)(out + (size_t)w * 64))[lane] = __floats2half2_rn(o0, o1);
}

// ---------------- Side-stream context ----------------
struct SideCtx {
    cudaStream_t side;
    cudaEvent_t evFork, evG1;
    SideCtx() {
        cudaStreamCreateWithFlags(&side, cudaStreamNonBlocking);
        cudaEventCreateWithFlags(&evFork, cudaEventDisableTiming);
        cudaEventCreateWithFlags(&evG1, cudaEventDisableTiming);
    }
};
static SideCtx g_ctx;

// ---------------- Host launcher ----------------
extern "C" void kernel_launch(void* const* d_in, const int* in_sizes, int n_in,
                              void* d_out, int out_size) {
    const float* x  = (const float*)d_in[0];
    const int*   ei = (const int*)d_in[1];
    const float* W1 = (const float*)d_in[2];
    const float* b1 = (const float*)d_in[3];
    const float* W2 = (const float*)d_in[4];
    const float* b2 = (const float*)d_in[5];
    const float* W3 = (const float*)d_in[6];
    const float* b3 = (const float*)d_in[7];
    const float* W4 = (const float*)d_in[8];
    const float* b4 = (const float*)d_in[9];
    float* out = (float*)d_out;

    const int M = in_sizes[0] / 128;
    const int E = in_sizes[1] / 2;

    __half *hb, *ab;
    float *Wf, *bf, *dinv;
    cudaGetSymbolAddress((void**)&hb, g_h);
    cudaGetSymbolAddress((void**)&ab, g_a);
    cudaGetSymbolAddress((void**)&Wf, g_Wf);
    cudaGetSymbolAddress((void**)&bf, g_bf);
    cudaGetSymbolAddress((void**)&dinv, g_dinv);

    const int smem128 = 128 * 32 * 4 + 128 * 136 * 2;   // 51200 B
    const int smem64  = 64 * 32 * 4 + 128 * 72 * 2;     // 26624 B
    cudaFuncSetAttribute((const void*)gemm_mma<128, 0, float, __half>,
                         cudaFuncAttributeMaxDynamicSharedMemorySize, smem128);
    cudaFuncSetAttribute((const void*)gemm_mma<64, 0, __half, __half>,
                         cudaFuncAttributeMaxDynamicSharedMemorySize, smem64);
    cudaFuncSetAttribute((const void*)gemm_mma<64, 1, __half, float>,
                         cudaFuncAttributeMaxDynamicSharedMemorySize, smem64);

    const int gemmBlocks = (M + 127) / 128;
    const int warpBlocks = (M * 32 + 255) / 256;
    const int NBZ = (M + 255) / 256;
    const int scanBlocks = (M + 1023) / 1024;

    // Fork: GEMM1 (unscaled; no CSR dependency) on side stream || CSR build on main stream.
    cudaEventRecord(g_ctx.evFork, 0);
    cudaStreamWaitEvent(g_ctx.side, g_ctx.evFork, 0);
    gemm_mma<128, 0, float, __half><<<gemmBlocks, 256, smem128, g_ctx.side>>>(x, W1, nullptr, hb, M);
    cudaEventRecord(g_ctx.evG1, g_ctx.side);

    prep_k<<<NBZ + 17, 256>>>(ei, 2 * E, M, W3, W4, b3, b4);
    hist_k<<<(E + 255) / 256, 256>>>(ei, E);
    scan_k<<<scanBlocks, 1024>>>(M, E);
    fill_k<<<(E + 255) / 256, 256>>>(ei, E);

    cudaStreamWaitEvent(0, g_ctx.evG1, 0);
    // Apply dinv scaling to GEMM1's output (dinv wasn't ready when it ran).
    scale_k<<<(M * 8 + 255) / 256, 256>>>(hb, M);
    agg_k<<<warpBlocks, 256>>>(hb, b1, ab, M);
    // GEMM2: dinv ready -> scale in epilogue.
    gemm_mma<64, 0, __half, __half><<<gemmBlocks, 256, smem64>>>(ab, W2, dinv, hb, M);
    agg_k<<<warpBlocks, 256>>>(hb, b2, ab, M);
    gemm_mma<64, 1, __half, float><<<gemmBlocks, 256, smem64>>>(ab, Wf, bf, out, M);
}